// round 7
// baseline (speedup 1.0000x reference)
#include <cuda_runtime.h>

#define BATCH 16
#define SEQY 2048
#define SEQX 2048
#define DIM 128
#define TY 64
#define TX 64
#define NTHREADS 256
#define NTILES (SEQX / TX)   // 32
#define YBLK (SEQY / TY)     // 32

// padded pitches (in floats)
#define YT_PITCH 68   // Yt[d][y], 272B rows -> 16B aligned, conflict-free LDS.128
#define XT_PITCH 68   // Xt[d][x]
#define XR_PITCH 132  // Xr[x][d], 528B rows
#define PT_PITCH 65   // Pt[x][y] (scalar access, odd pitch kills conflicts)

struct SmemLayout {
    float Yt[DIM * YT_PITCH];   // 34816 B
    float Xt[DIM * XT_PITCH];   // 34816 B
    float Xr[TX * XR_PITCH];    // 33792 B
    float Pt[TX * PT_PITCH];    // 16640 B
    float mrow[TY];
    float lrow[TY];
    float frow[TY];
    float red[16 * DIM];        // 8192 B
};  // ~129 KB total

__device__ float g_partial[BATCH * YBLK * DIM];
__device__ float g_ysum[BATCH * DIM];

// ---------------------------------------------------------------------------
// Main fused kernel: one block per (batch, 64-row y tile). Online softmax.
// ---------------------------------------------------------------------------
__global__ void __launch_bounds__(NTHREADS, 1)
attn_main_kernel(const float* __restrict__ Xg, const float* __restrict__ Yg)
{
    extern __shared__ float smem_f[];
    SmemLayout* sm = reinterpret_cast<SmemLayout*>(smem_f);
    const int tid = threadIdx.x;
    const int b   = blockIdx.x / YBLK;
    const int yb  = blockIdx.x % YBLK;

    const float* Ybase = Yg + ((size_t)(b * SEQY + yb * TY)) * DIM;
    const float* Xbase = Xg + (size_t)b * SEQX * DIM;

    // Load Y tile transposed: Yt[d][y] (one-time; store conflicts don't matter)
    #pragma unroll
    for (int it = 0; it < (TY * DIM) / NTHREADS; ++it) {
        int e = tid + it * NTHREADS;
        int y = e >> 7;
        int d = e & 127;
        sm->Yt[d * YT_PITCH + y] = Ybase[e];
    }
    if (tid < TY) { sm->mrow[tid] = -3.0e38f; sm->lrow[tid] = 0.f; }

    const int ty = tid >> 4;   // 16 y-groups of 4 rows
    const int tx = tid & 15;   // 16 x-groups of 4 cols (S) / 16 d-groups (PV)

    float acc[4][8];           // PV accumulator: 4 y-rows x 8 d (d = tx + 16*j)
    #pragma unroll
    for (int i = 0; i < 4; ++i)
        #pragma unroll
        for (int j = 0; j < 8; ++j) acc[i][j] = 0.f;

    for (int t = 0; t < NTILES; ++t) {
        __syncthreads();   // previous PV done before overwriting X tiles

        // Load X tile (64x128) into both layouts; gmem reads L2-resident.
        const float* Xtile = Xbase + (size_t)t * (TX * DIM);
        #pragma unroll
        for (int it = 0; it < (TX * DIM) / NTHREADS; ++it) {
            int e = tid + it * NTHREADS;
            int x = e >> 7;
            int d = e & 127;
            float v = Xtile[e];
            sm->Xt[d * XT_PITCH + x] = v;
            sm->Xr[x * XR_PITCH + d] = v;
        }
        __syncthreads();

        // ---- S = Y_tile @ X_tile^T  (outer product over k = d) ----
        float s[4][4];
        #pragma unroll
        for (int i = 0; i < 4; ++i)
            #pragma unroll
            for (int j = 0; j < 4; ++j) s[i][j] = 0.f;

        const float* ytp = sm->Yt + ty * 4;
        const float* xtp = sm->Xt + tx * 4;
        #pragma unroll 8
        for (int k = 0; k < DIM; ++k) {
            float4 a  = *reinterpret_cast<const float4*>(ytp + k * YT_PITCH);
            float4 bb = *reinterpret_cast<const float4*>(xtp + k * XT_PITCH);
            float av[4] = {a.x, a.y, a.z, a.w};
            float bv[4] = {bb.x, bb.y, bb.z, bb.w};
            #pragma unroll
            for (int i = 0; i < 4; ++i)
                #pragma unroll
                for (int j = 0; j < 4; ++j)
                    s[i][j] = fmaf(av[i], bv[j], s[i][j]);
        }
        // Store S transposed: Pt[x][y]
        #pragma unroll
        for (int j = 0; j < 4; ++j)
            #pragma unroll
            for (int i = 0; i < 4; ++i)
                sm->Pt[(tx * 4 + j) * PT_PITCH + (ty * 4 + i)] = s[i][j];

        __syncthreads();

        // ---- online softmax over this tile: 4 threads per row ----
        {
            const int r = tid >> 2;   // row 0..63
            const int q = tid & 3;    // quarter of the 64 x values
            float v[16];
            float mx = -3.0e38f;
            #pragma unroll
            for (int u = 0; u < 16; ++u) {
                float vv = sm->Pt[(q * 16 + u) * PT_PITCH + r];
                v[u] = vv;
                mx = fmaxf(mx, vv);
            }
            mx = fmaxf(mx, __shfl_xor_sync(0xffffffffu, mx, 1));
            mx = fmaxf(mx, __shfl_xor_sync(0xffffffffu, mx, 2));
            float m_old = sm->mrow[r];
            float m_new = fmaxf(m_old, mx);
            float sum = 0.f;
            #pragma unroll
            for (int u = 0; u < 16; ++u) {
                float p = __expf(v[u] - m_new);
                sum += p;
                sm->Pt[(q * 16 + u) * PT_PITCH + r] = p;
            }
            sum += __shfl_xor_sync(0xffffffffu, sum, 1);
            sum += __shfl_xor_sync(0xffffffffu, sum, 2);
            if (q == 0) {
                float f = __expf(m_old - m_new);   // exp(-huge) -> 0, no NaN
                sm->lrow[r] = sm->lrow[r] * f + sum;
                sm->mrow[r] = m_new;
                sm->frow[r] = f;
            }
        }
        __syncthreads();

        // ---- acc = acc * fac + P @ X_tile ----
        {
            float f[4];
            #pragma unroll
            for (int i = 0; i < 4; ++i) f[i] = sm->frow[ty * 4 + i];
            #pragma unroll
            for (int i = 0; i < 4; ++i)
                #pragma unroll
                for (int j = 0; j < 8; ++j) acc[i][j] *= f[i];

            const float* ptp = sm->Pt + ty * 4;
            const float* xrp = sm->Xr + tx;     // this thread owns d = tx + 16*j
            #pragma unroll 4
            for (int k = 0; k < TX; ++k) {
                float a0 = ptp[k * PT_PITCH + 0];
                float a1 = ptp[k * PT_PITCH + 1];
                float a2 = ptp[k * PT_PITCH + 2];
                float a3 = ptp[k * PT_PITCH + 3];
                #pragma unroll
                for (int j = 0; j < 8; ++j) {
                    float bvv = xrp[k * XR_PITCH + 16 * j];
                    acc[0][j] = fmaf(a0, bvv, acc[0][j]);
                    acc[1][j] = fmaf(a1, bvv, acc[1][j]);
                    acc[2][j] = fmaf(a2, bvv, acc[2][j]);
                    acc[3][j] = fmaf(a3, bvv, acc[3][j]);
                }
            }
        }
    }

    // ---- epilogue: sum_y acc[y][d] / l[y] over this block's 64 rows ----
    float inv[4];
    #pragma unroll
    for (int i = 0; i < 4; ++i) inv[i] = 1.0f / sm->lrow[ty * 4 + i];
    #pragma unroll
    for (int j = 0; j < 8; ++j) {
        float p = acc[0][j] * inv[0] + acc[1][j] * inv[1]
                + acc[2][j] * inv[2] + acc[3][j] * inv[3];
        sm->red[ty * DIM + tx + 16 * j] = p;
    }
    __syncthreads();
    if (tid < DIM) {
        float ssum = 0.f;
        #pragma unroll
        for (int g = 0; g < 16; ++g) ssum += sm->red[g * DIM + tid];
        g_partial[blockIdx.x * DIM + tid] = ssum;
    }
}

// ---------------------------------------------------------------------------
// ysum[b][d] = sum_y Y[b][y][d]   (visual = ysum . x / SY, rank-1 trick)
// ---------------------------------------------------------------------------
__global__ void ysum_kernel(const float* __restrict__ Yg)
{
    __shared__ float buf[2 * DIM];
    int b = blockIdx.x;
    int d = threadIdx.x & 127;
    int h = threadIdx.x >> 7;   // 0/1: even/odd y
    const float* p = Yg + ((size_t)b * SEQY + h) * DIM + d;
    float s0 = 0.f, s1 = 0.f, s2 = 0.f, s3 = 0.f;
    for (int y = 0; y < SEQY / 2; y += 4) {
        s0 += p[(size_t)(2 * (y + 0)) * DIM];
        s1 += p[(size_t)(2 * (y + 1)) * DIM];
        s2 += p[(size_t)(2 * (y + 2)) * DIM];
        s3 += p[(size_t)(2 * (y + 3)) * DIM];
    }
    buf[h * DIM + d] = (s0 + s1) + (s2 + s3);
    __syncthreads();
    if (h == 0) g_ysum[b * DIM + d] = buf[d] + buf[DIM + d];
}

// ---------------------------------------------------------------------------
// visual[b][x] = dot(ysum[b], X[b][x]) / SY   (one warp per x)
// ---------------------------------------------------------------------------
__global__ void visual_kernel(const float* __restrict__ Xg, float* __restrict__ out)
{
    __shared__ float ys[DIM];
    const int bpb = SEQX / 8;    // blocks per batch
    int b  = blockIdx.x / bpb;
    int x0 = (blockIdx.x % bpb) * 8;
    if (threadIdx.x < DIM) ys[threadIdx.x] = g_ysum[b * DIM + threadIdx.x];
    __syncthreads();
    int w    = threadIdx.x >> 5;
    int lane = threadIdx.x & 31;
    int x    = x0 + w;
    const float* xp = Xg + ((size_t)b * SEQX + x) * DIM + lane * 4;
    float4 xv = *reinterpret_cast<const float4*>(xp);
    float4 yv = *reinterpret_cast<const float4*>(ys + lane * 4);
    float sdot = xv.x * yv.x + xv.y * yv.y + xv.z * yv.z + xv.w * yv.w;
    #pragma unroll
    for (int o = 16; o > 0; o >>= 1)
        sdot += __shfl_xor_sync(0xffffffffu, sdot, o);
    if (lane == 0) out[(size_t)b * SEQX + x] = sdot * (1.0f / SEQY);
}

// ---------------------------------------------------------------------------
// out[b][d] = sum over y-blocks of partials / SY
// ---------------------------------------------------------------------------
__global__ void outred_kernel(float* __restrict__ out)
{
    int b = blockIdx.x;
    int d = threadIdx.x;
    float s = 0.f;
    #pragma unroll 8
    for (int g = 0; g < YBLK; ++g)
        s += g_partial[(b * YBLK + g) * DIM + d];
    out[(size_t)BATCH * SEQX + b * DIM + d] = s * (1.0f / SEQY);
}

extern "C" void kernel_launch(void* const* d_in, const int* in_sizes, int n_in,
                              void* d_out, int out_size)
{
    const float* X = (const float*)d_in[0];   // input_x [B, SX, D]
    const float* Y = (const float*)d_in[1];   // input_y [B, SY, D]
    float* out = (float*)d_out;               // [B*SX visual | B*D out]

    (void)in_sizes; (void)n_in; (void)out_size;

    cudaFuncSetAttribute(attn_main_kernel,
                         cudaFuncAttributeMaxDynamicSharedMemorySize,
                         (int)sizeof(SmemLayout));

    ysum_kernel<<<BATCH, 256>>>(Y);
    visual_kernel<<<BATCH * SEQX / 8, 256>>>(X, out);
    attn_main_kernel<<<BATCH * YBLK, NTHREADS, sizeof(SmemLayout)>>>(X, Y);
    outred_kernel<<<BATCH, DIM>>>(out);
}